// round 14
// baseline (speedup 1.0000x reference)
#include <cuda_runtime.h>
#include <cuda_fp16.h>
#include <cstdint>

#define N_SRC0 100000
#define N_DST0 20000
#define N_DST1 4000
#define E0V 640000
#define E1V 128000
#define IN_F 512
#define HID_F 512
#define OUT_F 256

// ---------------- scratch (device globals) ----------------------------------
__device__ __half g_xh[(size_t)N_SRC0 * IN_F];       // x, fp16 (unscaled)
__device__ __half g_agg0h[(size_t)N_DST0 * IN_F];
__device__ __half g_h1h[(size_t)N_DST0 * HID_F];
__device__ __half g_agg1h[(size_t)N_DST1 * HID_F];
__device__ __half g_w1h[512 * 512];
__device__ __half g_w2h[512 * 256];

// count layout: [C_DST0 (20000) | C_DST1 (4000) | C_SRC1 (20000) | C_SRC0 (100000)]
#define OFF_C_DST0 0
#define OFF_C_DST1 20000
#define OFF_C_SRC1 24000
#define OFF_C_SRC0 44000
#define N_CNT      144000
#define N_SCAN     24000
__device__ int g_ints[N_CNT];
__device__ float g_norm[N_CNT];     // din0 | din1 | outn1 | outn0

__device__ int g_rpc[N_SCAN + 1];
__device__ int g_cur[N_SCAN];       // running cursors, init = rpc by scan kernel
__device__ int g_col0[E0V];
__device__ int g_col1[E1V];

// ---------------- kernels ----------------------------------------------------

__global__ void k_zeroi(int* __restrict__ b, int nb) {
    int stride = gridDim.x * blockDim.x;
    for (int i = blockIdx.x * blockDim.x + threadIdx.x; i < nb; i += stride)
        b[i] = 0;
}

__device__ __forceinline__ uint4 cvt4(float4 v0, float4 v1) {
    __half2 h0 = __floats2half2_rn(v0.x, v0.y), h1 = __floats2half2_rn(v0.z, v0.w);
    __half2 h2 = __floats2half2_rn(v1.x, v1.y), h3 = __floats2half2_rn(v1.z, v1.w);
    return make_uint4(*(uint32_t*)&h0, *(uint32_t*)&h1,
                      *(uint32_t*)&h2, *(uint32_t*)&h3);
}

// x->fp16 and W->fp16 (side stream; independent of graph topology work)
#define XP_BLOCKS 25000        // N_SRC0*IN_F/8 threads, 2 float4 each
#define WP_BLOCKS 192
__global__ void k_prep_xw(const float* __restrict__ x, __half* __restrict__ xh,
                          const float* __restrict__ W1, const float* __restrict__ W2,
                          __half* __restrict__ w1h, __half* __restrict__ w2h) {
    int b = blockIdx.x;
    if (b < XP_BLOCKS) {
        size_t i = (size_t)b * 256 + threadIdx.x;
        const float4* xp = reinterpret_cast<const float4*>(x) + 2 * i;
        reinterpret_cast<uint4*>(xh)[i] = cvt4(__ldg(xp), __ldg(xp + 1));
    } else {
        int i = (b - XP_BLOCKS) * 256 + threadIdx.x;
        if (i < 32768) {
            const float4* wp = reinterpret_cast<const float4*>(W1) + 2 * i;
            reinterpret_cast<uint4*>(w1h)[i] = cvt4(__ldg(wp), __ldg(wp + 1));
        } else {
            int j = i - 32768;
            const float4* wp = reinterpret_cast<const float4*>(W2) + 2 * j;
            reinterpret_cast<uint4*>(w2h)[j] = cvt4(__ldg(wp), __ldg(wp + 1));
        }
    }
}

__global__ void k_count(const int* __restrict__ s0, const int* __restrict__ d0,
                        const int* __restrict__ s1, const int* __restrict__ d1,
                        int* __restrict__ ints) {
    int i = blockIdx.x * blockDim.x + threadIdx.x;
    if (i < E0V) {
        atomicAdd(ints + OFF_C_SRC0 + __ldg(s0 + i), 1);
        atomicAdd(ints + OFF_C_DST0 + __ldg(d0 + i), 1);
    } else {
        int j = i - E0V;
        if (j < E1V) {
            atomicAdd(ints + OFF_C_SRC1 + __ldg(s1 + j), 1);
            atomicAdd(ints + OFF_C_DST1 + __ldg(d1 + j), 1);
        }
    }
}

// single-block scan over 24000 counts; also writes cursor copy (= exclusive rp)
__global__ void k_scan_one(const int* __restrict__ cnt, int* __restrict__ rp,
                           int* __restrict__ cur, int n) {
    __shared__ int ws[32];
    const int C = 24;
    int tid = threadIdx.x;
    int lane = tid & 31, warp = tid >> 5;
    int base = tid * C;
    int vals[C];
    int sum = 0;
#pragma unroll
    for (int j = 0; j < C; j++) {
        int idx = base + j;
        int v = (idx < n) ? cnt[idx] : 0;
        vals[j] = v;
        sum += v;
    }
    int s = sum;
#pragma unroll
    for (int d = 1; d < 32; d <<= 1) {
        int t = __shfl_up_sync(0xffffffffu, s, d);
        if (lane >= d) s += t;
    }
    if (lane == 31) ws[warp] = s;
    __syncthreads();
    if (warp == 0) {
        int w = ws[lane];
#pragma unroll
        for (int d = 1; d < 32; d <<= 1) {
            int t = __shfl_up_sync(0xffffffffu, w, d);
            if (lane >= d) w += t;
        }
        ws[lane] = w;
    }
    __syncthreads();
    int run = s - sum + (warp > 0 ? ws[warp - 1] : 0);   // exclusive prefix
    if (tid == 0) rp[0] = 0;
#pragma unroll
    for (int j = 0; j < C; j++) {
        int idx = base + j;
        if (idx < n) cur[idx] = run;
        run += vals[j];
        if (idx < n) rp[idx + 1] = run;
    }
}

// fused: all norms + both CSC fills (single atomic returns position)
__global__ void k_fill_norm(const int* __restrict__ src0, const int* __restrict__ dst0,
                            const int* __restrict__ src1, const int* __restrict__ dst1,
                            int* __restrict__ cur, const int* __restrict__ ints,
                            int* __restrict__ col0, int* __restrict__ col1,
                            float* __restrict__ nrm) {
    int i = blockIdx.x * blockDim.x + threadIdx.x;
    if (i < N_CNT) nrm[i] = rsqrtf(fmaxf((float)ints[i], 1.0f));
    if (i < E0V) {
        int k = __ldg(dst0 + i);
        int pos = atomicAdd(cur + k, 1);
        col0[pos] = __ldg(src0 + i);
    } else {
        int j = i - E0V;
        if (j < E1V) {
            int k = __ldg(dst1 + j);
            int pos = atomicAdd(cur + OFF_C_DST1 + k, 1) - E0V;
            col1[pos] = __ldg(src1 + j);
        }
    }
}

// ---------------- gather with per-edge scale (layer 1) ----------------------
__global__ void k_gather_es(const __half* __restrict__ h,
                            const int* __restrict__ rp, const int* __restrict__ col,
                            const float* __restrict__ escale, const float* __restrict__ din,
                            __half* __restrict__ aggh, int n_dst) {
    int w = (blockIdx.x * blockDim.x + threadIdx.x) >> 5;
    int lane = threadIdx.x & 31;
    if (w >= n_dst) return;
    int beg = rp[w], end = rp[w + 1];
    float acc[16];
#pragma unroll
    for (int i = 0; i < 16; i++) acc[i] = 0.f;
    int e = beg;
    for (; e + 1 < end; e += 2) {
        int s0 = __ldg(col + e), s1 = __ldg(col + e + 1);
        float c0 = __ldg(escale + s0), c1 = __ldg(escale + s1);
        const uint4* hp0 = reinterpret_cast<const uint4*>(h + (size_t)s0 * 512) + 2 * lane;
        const uint4* hp1 = reinterpret_cast<const uint4*>(h + (size_t)s1 * 512) + 2 * lane;
        uint4 p0 = __ldg(hp0), q0 = __ldg(hp0 + 1);
        uint4 p1 = __ldg(hp1), q1 = __ldg(hp1 + 1);
        const uint32_t r0[8] = {p0.x, p0.y, p0.z, p0.w, q0.x, q0.y, q0.z, q0.w};
        const uint32_t r1[8] = {p1.x, p1.y, p1.z, p1.w, q1.x, q1.y, q1.z, q1.w};
#pragma unroll
        for (int i = 0; i < 8; i++) {
            float2 f0 = __half22float2(*(const __half2*)&r0[i]);
            float2 f1 = __half22float2(*(const __half2*)&r1[i]);
            acc[2 * i]     = fmaf(f0.x, c0, acc[2 * i]);
            acc[2 * i + 1] = fmaf(f0.y, c0, acc[2 * i + 1]);
            acc[2 * i]     = fmaf(f1.x, c1, acc[2 * i]);
            acc[2 * i + 1] = fmaf(f1.y, c1, acc[2 * i + 1]);
        }
    }
    if (e < end) {
        int s = __ldg(col + e);
        float c = __ldg(escale + s);
        const uint4* hp = reinterpret_cast<const uint4*>(h + (size_t)s * 512) + 2 * lane;
        uint4 p = __ldg(hp), q = __ldg(hp + 1);
        const uint32_t pr[8] = {p.x, p.y, p.z, p.w, q.x, q.y, q.z, q.w};
#pragma unroll
        for (int i = 0; i < 8; i++) {
            float2 f = __half22float2(*(const __half2*)&pr[i]);
            acc[2 * i]     = fmaf(f.x, c, acc[2 * i]);
            acc[2 * i + 1] = fmaf(f.y, c, acc[2 * i + 1]);
        }
    }
    float d = din[w];
    uint32_t o[8];
#pragma unroll
    for (int i = 0; i < 8; i++) {
        __half2 h2 = __floats2half2_rn(acc[2 * i] * d, acc[2 * i + 1] * d);
        o[i] = *(uint32_t*)&h2;
    }
    uint4* op = reinterpret_cast<uint4*>(aggh + (size_t)w * 512) + 2 * lane;
    op[0] = make_uint4(o[0], o[1], o[2], o[3]);
    op[1] = make_uint4(o[4], o[5], o[6], o[7]);
}

// ---------------- plain gather (layer 2) -------------------------------------
__global__ void k_gather_ns(const __half* __restrict__ h,
                            const int* __restrict__ rp, const int* __restrict__ col,
                            const float* __restrict__ din,
                            __half* __restrict__ aggh, int n_dst, int ebase) {
    int w = (blockIdx.x * blockDim.x + threadIdx.x) >> 5;
    int lane = threadIdx.x & 31;
    if (w >= n_dst) return;
    int beg = rp[w] - ebase, end = rp[w + 1] - ebase;
    float acc[16];
#pragma unroll
    for (int i = 0; i < 16; i++) acc[i] = 0.f;
    for (int e = beg; e < end; e++) {
        int s = __ldg(col + e);
        const uint4* hp = reinterpret_cast<const uint4*>(h + (size_t)s * 512) + 2 * lane;
        uint4 p = __ldg(hp), q = __ldg(hp + 1);
        const uint32_t pr[8] = {p.x, p.y, p.z, p.w, q.x, q.y, q.z, q.w};
#pragma unroll
        for (int i = 0; i < 8; i++) {
            float2 f = __half22float2(*(const __half2*)&pr[i]);
            acc[2 * i] += f.x;
            acc[2 * i + 1] += f.y;
        }
    }
    float d = din[w];
    uint32_t o[8];
#pragma unroll
    for (int i = 0; i < 8; i++) {
        __half2 h2 = __floats2half2_rn(acc[2 * i] * d, acc[2 * i + 1] * d);
        o[i] = *(uint32_t*)&h2;
    }
    uint4* op = reinterpret_cast<uint4*>(aggh + (size_t)w * 512) + 2 * lane;
    op[0] = make_uint4(o[0], o[1], o[2], o[3]);
    op[1] = make_uint4(o[4], o[5], o[6], o[7]);
}

// ---------------- fp16 HMMA GEMM: C = rowscale * relu(A @ B + bias) ----------
#define PADK 40
#define PADN 136
#define SZ_A (64 * PADK * 2)
#define SZ_B (32 * PADN * 2)
#define STAGE_BYTES (SZ_A + SZ_B)
#define GSM_TOTAL (2 * STAGE_BYTES)
#define O_AH 0
#define O_BH SZ_A

__device__ __forceinline__ void ldm4(uint32_t* f, uint32_t addr) {
    asm volatile("ldmatrix.sync.aligned.m8n8.x4.shared.b16 {%0,%1,%2,%3}, [%4];"
                 : "=r"(f[0]), "=r"(f[1]), "=r"(f[2]), "=r"(f[3]) : "r"(addr));
}
__device__ __forceinline__ void ldm4t(uint32_t* f, uint32_t addr) {
    asm volatile("ldmatrix.sync.aligned.m8n8.x4.trans.shared.b16 {%0,%1,%2,%3}, [%4];"
                 : "=r"(f[0]), "=r"(f[1]), "=r"(f[2]), "=r"(f[3]) : "r"(addr));
}
__device__ __forceinline__ void mma16816h(float* c, const uint32_t* a, const uint32_t* b) {
    asm volatile("mma.sync.aligned.m16n8k16.row.col.f32.f16.f16.f32 "
                 "{%0,%1,%2,%3}, {%4,%5,%6,%7}, {%8,%9}, {%0,%1,%2,%3};"
                 : "+f"(c[0]), "+f"(c[1]), "+f"(c[2]), "+f"(c[3])
                 : "r"(a[0]), "r"(a[1]), "r"(a[2]), "r"(a[3]), "r"(b[0]), "r"(b[1]));
}

__global__ __launch_bounds__(256, 2) void k_gemm_h(
    const __half* __restrict__ A, const __half* __restrict__ B,
    const float* __restrict__ bias, const float* __restrict__ rscale,
    void* __restrict__ Cv, int M, int Nt, int out_half) {
    extern __shared__ char smem[];
    int tid = threadIdx.x;
    int wid = tid >> 5, lane = tid & 31;
    int wm = (wid >> 2) * 32;
    int wn = (wid & 3) * 32;
    int row0 = blockIdx.y * 64, col0 = blockIdx.x * 128;

    int sr = tid >> 2;
    int sk = (tid & 3) * 8;
    int rowA = row0 + sr;
    bool aval = rowA < M;
    const __half* gA = A + (size_t)(aval ? rowA : 0) * 512 + sk;
    int bk = tid >> 3;
    int bn = (tid & 7) * 16;
    const __half* gB = B + (size_t)bk * Nt + col0 + bn;

    uint32_t ubase = (uint32_t)__cvta_generic_to_shared(smem);

    int aRow = wm + (lane & 15);
    int aCol = (lane >> 4) << 3;
    int kIdx = (lane & 7) + (((lane >> 3) & 1) << 3);
    int nOff = (lane >> 4) << 3;

    float acc[2][4][4];
#pragma unroll
    for (int i = 0; i < 2; i++)
#pragma unroll
        for (int j = 0; j < 4; j++)
#pragma unroll
            for (int k = 0; k < 4; k++) acc[i][j][k] = 0.f;

    {
        char* st = smem;
        uint4 va = aval ? __ldg((const uint4*)gA) : make_uint4(0, 0, 0, 0);
        *(uint4*)(st + O_AH + (sr * PADK + sk) * 2) = va;
        uint4 vb0 = __ldg((const uint4*)gB);
        uint4 vb1 = __ldg((const uint4*)gB + 1);
        *(uint4*)(st + O_BH + (bk * PADN + bn) * 2) = vb0;
        *(uint4*)(st + O_BH + (bk * PADN + bn) * 2 + 16) = vb1;
    }
    __syncthreads();

    for (int c = 0; c < 16; c++) {
        uint32_t ub = ubase + (c & 1) * STAGE_BYTES;

        uint4 pa, pb0, pb1;
        if (c < 15) {
            pa = aval ? __ldg((const uint4*)(gA + (c + 1) * 32)) : make_uint4(0, 0, 0, 0);
            const __half* nb = gB + (size_t)(c + 1) * 32 * Nt;
            pb0 = __ldg((const uint4*)nb);
            pb1 = __ldg((const uint4*)nb + 1);
        }

#pragma unroll
        for (int ks = 0; ks < 32; ks += 16) {
            uint32_t ah[2][4], bh[4][2];
#pragma unroll
            for (int mt = 0; mt < 2; mt++) {
                uint32_t off = ((uint32_t)((aRow + mt * 16) * PADK + ks + aCol)) * 2;
                ldm4(ah[mt], ub + O_AH + off);
            }
#pragma unroll
            for (int ntp = 0; ntp < 2; ntp++) {
                uint32_t off = ((uint32_t)((ks + kIdx) * PADN + wn + ntp * 16 + nOff)) * 2;
                uint32_t t[4];
                ldm4t(t, ub + O_BH + off);
                bh[ntp * 2][0] = t[0]; bh[ntp * 2][1] = t[1];
                bh[ntp * 2 + 1][0] = t[2]; bh[ntp * 2 + 1][1] = t[3];
            }
#pragma unroll
            for (int mt = 0; mt < 2; mt++)
#pragma unroll
                for (int nt = 0; nt < 4; nt++)
                    mma16816h(acc[mt][nt], ah[mt], bh[nt]);
        }

        if (c < 15) {
            char* st = smem + ((c & 1) ^ 1) * STAGE_BYTES;
            *(uint4*)(st + O_AH + (sr * PADK + sk) * 2) = pa;
            *(uint4*)(st + O_BH + (bk * PADN + bn) * 2) = pb0;
            *(uint4*)(st + O_BH + (bk * PADN + bn) * 2 + 16) = pb1;
        }
        __syncthreads();
    }

    int erow = row0 + wm + (lane >> 2);
    int ecol0 = col0 + wn + (lane & 3) * 2;
#pragma unroll
    for (int nt = 0; nt < 4; nt++) {
        int cc = ecol0 + nt * 8;
        float bx = __ldg(bias + cc), by = __ldg(bias + cc + 1);
#pragma unroll
        for (int mt = 0; mt < 2; mt++) {
#pragma unroll
            for (int hpart = 0; hpart < 2; hpart++) {
                int rr = erow + mt * 16 + hpart * 8;
                if (rr < M) {
                    float rs = rscale ? __ldg(rscale + rr) : 1.0f;
                    float ox = fmaxf(acc[mt][nt][2 * hpart] + bx, 0.f) * rs;
                    float oy = fmaxf(acc[mt][nt][2 * hpart + 1] + by, 0.f) * rs;
                    if (out_half) {
                        __half2 h2 = __floats2half2_rn(ox, oy);
                        *(uint32_t*)((__half*)Cv + (size_t)rr * Nt + cc) = *(uint32_t*)&h2;
                    } else {
                        *(float2*)((float*)Cv + (size_t)rr * Nt + cc) = make_float2(ox, oy);
                    }
                }
            }
        }
    }
}

// ---------------- launch ----------------------------------------------------

extern "C" void kernel_launch(void* const* d_in, const int* in_sizes, int n_in,
                              void* d_out, int out_size) {
    const float* x    = (const float*)d_in[0];
    const int*   src0 = (const int*)d_in[1];
    const int*   dst0 = (const int*)d_in[2];
    const int*   src1 = (const int*)d_in[3];
    const int*   dst1 = (const int*)d_in[4];
    const float* W1   = (const float*)d_in[5];
    const float* b1   = (const float*)d_in[6];
    const float* W2   = (const float*)d_in[7];
    const float* b2   = (const float*)d_in[8];
    float* out = (float*)d_out;

    float* nrm;
    int *ints, *rpc, *cur, *col0, *col1;
    __half *xh, *agg0h, *h1h, *agg1h, *w1h, *w2h;
    cudaGetSymbolAddress((void**)&nrm,   g_norm);
    cudaGetSymbolAddress((void**)&ints,  g_ints);
    cudaGetSymbolAddress((void**)&rpc,   g_rpc);
    cudaGetSymbolAddress((void**)&cur,   g_cur);
    cudaGetSymbolAddress((void**)&col0,  g_col0);
    cudaGetSymbolAddress((void**)&col1,  g_col1);
    cudaGetSymbolAddress((void**)&xh,    g_xh);
    cudaGetSymbolAddress((void**)&agg0h, g_agg0h);
    cudaGetSymbolAddress((void**)&h1h,   g_h1h);
    cudaGetSymbolAddress((void**)&agg1h, g_agg1h);
    cudaGetSymbolAddress((void**)&w1h,   g_w1h);
    cudaGetSymbolAddress((void**)&w2h,   g_w2h);

    static cudaStream_t s2 = nullptr;
    static cudaEvent_t evA = nullptr, evB = nullptr;
    if (!s2) {
        cudaStreamCreateWithFlags(&s2, cudaStreamNonBlocking);
        cudaEventCreateWithFlags(&evA, cudaEventDisableTiming);
        cudaEventCreateWithFlags(&evB, cudaEventDisableTiming);
        cudaFuncSetAttribute(k_gemm_h, cudaFuncAttributeMaxDynamicSharedMemorySize,
                             GSM_TOTAL);
    }

    const float* din0  = nrm + OFF_C_DST0;
    const float* din1  = nrm + OFF_C_DST1;
    const float* outn1 = nrm + OFF_C_SRC1;
    const float* outn0 = nrm + OFF_C_SRC0;

    // ---- fork: side stream converts x/W to fp16 (independent of topology)
    cudaEventRecord(evA, 0);
    cudaStreamWaitEvent(s2, evA, 0);
    k_prep_xw<<<XP_BLOCKS + WP_BLOCKS, 256, 0, s2>>>(x, xh, W1, W2, w1h, w2h);
    cudaEventRecord(evB, s2);

    // ---- main stream: topology chain
    k_zeroi<<<128, 256>>>(ints, N_CNT);
    k_count<<<(E0V + E1V + 255) / 256, 256>>>(src0, dst0, src1, dst1, ints);
    k_scan_one<<<1, 1024>>>(ints, rpc, cur, N_SCAN);
    k_fill_norm<<<(E0V + E1V + 255) / 256, 256>>>(src0, dst0, src1, dst1,
                                                  cur, ints, col0, col1, nrm);

    // ---- join: gathers need both branches
    cudaStreamWaitEvent(0, evB, 0);

    // layer-1 gather: agg0h[d] = din0[d] * sum outn0[s]*xh[s]
    k_gather_es<<<(N_DST0 * 32 + 255) / 256, 256>>>(xh, rpc, col0, outn0, din0,
                                                    agg0h, N_DST0);

    // GEMM1: h1h = outn1[row] * relu(agg0h @ W1h + b1)  (fp16 out)
    {
        dim3 grid(HID_F / 128, (N_DST0 + 63) / 64);
        k_gemm_h<<<grid, 256, GSM_TOTAL>>>(agg0h, w1h, b1, outn1, h1h,
                                           N_DST0, HID_F, 1);
    }

    // layer-2 gather: agg1h[d] = din1[d] * sum h1h[s]
    k_gather_ns<<<(N_DST1 * 32 + 255) / 256, 256>>>(h1h, rpc + OFF_C_DST1, col1, din1,
                                                    agg1h, N_DST1, E0V);

    // GEMM2: out = relu(agg1h @ W2h + b2)  (fp32 out)
    {
        dim3 grid(OUT_F / 128, (N_DST1 + 63) / 64);
        k_gemm_h<<<grid, 256, GSM_TOTAL>>>(agg1h, w2h, b2, nullptr, out,
                                           N_DST1, OUT_F, 0);
    }
}

// round 15
// speedup vs baseline: 1.1111x; 1.1111x over previous
#include <cuda_runtime.h>
#include <cuda_fp16.h>
#include <cstdint>

#define N_SRC0 100000
#define N_DST0 20000
#define N_DST1 4000
#define E0V 640000
#define E1V 128000
#define IN_F 512
#define HID_F 512
#define OUT_F 256

// ---------------- scratch (device globals) ----------------------------------
__device__ __half g_xh[(size_t)N_SRC0 * IN_F];       // x, fp16 (unscaled)
__device__ __half g_agg0h[(size_t)N_DST0 * IN_F];
__device__ __half g_h1h[(size_t)N_DST0 * HID_F];
__device__ __half g_agg1h[(size_t)N_DST1 * HID_F];
__device__ __half g_w1h[512 * 512];
__device__ __half g_w2h[512 * 256];

// count layout: [C_DST0 (20000) | C_DST1 (4000) | C_SRC1 (20000) | C_SRC0 (100000)]
#define OFF_C_DST0 0
#define OFF_C_DST1 20000
#define OFF_C_SRC1 24000
#define OFF_C_SRC0 44000
#define N_CNT      144000
#define N_SCAN     24000
__device__ int g_ints[N_CNT];
__device__ float g_norm[N_CNT];     // din0 | din1 | outn1 | outn0

__device__ int g_rpc[N_SCAN + 1];
__device__ int g_cur[N_SCAN];       // running cursors, init = exclusive prefix
__device__ int g_col0[E0V];
__device__ int g_col1[E1V];
__device__ int g_part[64];

// ---------------- fused prep: x->fp16, W->fp16, degree counts ---------------
#define XP_BLOCKS 25000        // N_SRC0*IN_F/8 threads, 2 float4 each
#define WP_BLOCKS 192
#define CNT_BLOCKS 3000

__global__ void k_zeroi(int* __restrict__ b, int nb) {
    int stride = gridDim.x * blockDim.x;
    for (int i = blockIdx.x * blockDim.x + threadIdx.x; i < nb; i += stride)
        b[i] = 0;
}

__device__ __forceinline__ uint4 cvt4(float4 v0, float4 v1) {
    __half2 h0 = __floats2half2_rn(v0.x, v0.y), h1 = __floats2half2_rn(v0.z, v0.w);
    __half2 h2 = __floats2half2_rn(v1.x, v1.y), h3 = __floats2half2_rn(v1.z, v1.w);
    return make_uint4(*(uint32_t*)&h0, *(uint32_t*)&h1,
                      *(uint32_t*)&h2, *(uint32_t*)&h3);
}

__global__ void k_prep(const float* __restrict__ x, __half* __restrict__ xh,
                       const float* __restrict__ W1, const float* __restrict__ W2,
                       __half* __restrict__ w1h, __half* __restrict__ w2h,
                       const int* __restrict__ s0, const int* __restrict__ d0,
                       const int* __restrict__ s1, const int* __restrict__ d1,
                       int* __restrict__ ints) {
    int b = blockIdx.x;
    if (b < XP_BLOCKS) {
        size_t i = (size_t)b * 256 + threadIdx.x;
        const float4* xp = reinterpret_cast<const float4*>(x) + 2 * i;
        reinterpret_cast<uint4*>(xh)[i] = cvt4(__ldg(xp), __ldg(xp + 1));
    } else if (b < XP_BLOCKS + WP_BLOCKS) {
        int i = (b - XP_BLOCKS) * 256 + threadIdx.x;
        if (i < 32768) {
            const float4* wp = reinterpret_cast<const float4*>(W1) + 2 * i;
            reinterpret_cast<uint4*>(w1h)[i] = cvt4(__ldg(wp), __ldg(wp + 1));
        } else {
            int j = i - 32768;
            const float4* wp = reinterpret_cast<const float4*>(W2) + 2 * j;
            reinterpret_cast<uint4*>(w2h)[j] = cvt4(__ldg(wp), __ldg(wp + 1));
        }
    } else {
        int i = (b - XP_BLOCKS - WP_BLOCKS) * 256 + threadIdx.x;
        if (i < E0V) {
            atomicAdd(ints + OFF_C_SRC0 + __ldg(s0 + i), 1);
            atomicAdd(ints + OFF_C_DST0 + __ldg(d0 + i), 1);
        } else {
            int j = i - E0V;
            if (j < E1V) {
                atomicAdd(ints + OFF_C_SRC1 + __ldg(s1 + j), 1);
                atomicAdd(ints + OFF_C_DST1 + __ldg(d1 + j), 1);
            }
        }
    }
}

// ---- hierarchical scan: 24 blocks x 1024, one element/thread ---------------
__global__ void k_scan1(const int* __restrict__ cnt, int* __restrict__ rp,
                        int* __restrict__ cur, int* __restrict__ part, int n) {
    __shared__ int ws[32];
    int tid = threadIdx.x;
    int lane = tid & 31, warp = tid >> 5;
    int i = blockIdx.x * 1024 + tid;
    int v = (i < n) ? cnt[i] : 0;
    int s = v;
#pragma unroll
    for (int d = 1; d < 32; d <<= 1) {
        int t = __shfl_up_sync(0xffffffffu, s, d);
        if (lane >= d) s += t;
    }
    if (lane == 31) ws[warp] = s;
    __syncthreads();
    if (warp == 0) {
        int w = ws[lane];
#pragma unroll
        for (int d = 1; d < 32; d <<= 1) {
            int t = __shfl_up_sync(0xffffffffu, w, d);
            if (lane >= d) w += t;
        }
        ws[lane] = w;
    }
    __syncthreads();
    if (warp > 0) s += ws[warp - 1];
    if (i < n) {
        rp[i + 1] = s;
        cur[i] = s - v;       // exclusive
    }
    if (tid == 1023) part[blockIdx.x] = s;
}

__global__ void k_scan2(int* __restrict__ part, int nb, int* __restrict__ rp) {
    int tid = threadIdx.x;       // 32 threads, nb <= 32
    int v = (tid < nb) ? part[tid] : 0;
    int s = v;
#pragma unroll
    for (int d = 1; d < 32; d <<= 1) {
        int t = __shfl_up_sync(0xffffffffu, s, d);
        if (tid >= d) s += t;
    }
    if (tid < nb) part[tid] = s - v;   // exclusive block offsets
    if (tid == 0) rp[0] = 0;
}

__global__ void k_scan3(int* __restrict__ rp, int* __restrict__ cur,
                        const int* __restrict__ part, int n) {
    int b = blockIdx.x;
    if (b == 0) return;
    int i = b * 1024 + threadIdx.x;
    if (i < n) {
        int off = part[b];
        rp[i + 1] += off;
        cur[i] += off;
    }
}

// fused: all norms + both CSC fills (single atomic returns position)
__global__ void k_fill_norm(const int* __restrict__ src0, const int* __restrict__ dst0,
                            const int* __restrict__ src1, const int* __restrict__ dst1,
                            int* __restrict__ cur, const int* __restrict__ ints,
                            int* __restrict__ col0, int* __restrict__ col1,
                            float* __restrict__ nrm) {
    int i = blockIdx.x * blockDim.x + threadIdx.x;
    if (i < N_CNT) nrm[i] = rsqrtf(fmaxf((float)ints[i], 1.0f));
    if (i < E0V) {
        int k = __ldg(dst0 + i);
        int pos = atomicAdd(cur + k, 1);
        col0[pos] = __ldg(src0 + i);
    } else {
        int j = i - E0V;
        if (j < E1V) {
            int k = __ldg(dst1 + j);
            int pos = atomicAdd(cur + OFF_C_DST1 + k, 1) - E0V;
            col1[pos] = __ldg(src1 + j);
        }
    }
}

// ---------------- gather with per-edge scale (layer 1) ----------------------
__global__ void k_gather_es(const __half* __restrict__ h,
                            const int* __restrict__ rp, const int* __restrict__ col,
                            const float* __restrict__ escale, const float* __restrict__ din,
                            __half* __restrict__ aggh, int n_dst) {
    int w = (blockIdx.x * blockDim.x + threadIdx.x) >> 5;
    int lane = threadIdx.x & 31;
    if (w >= n_dst) return;
    int beg = rp[w], end = rp[w + 1];
    float acc[16];
#pragma unroll
    for (int i = 0; i < 16; i++) acc[i] = 0.f;
    int e = beg;
    for (; e + 1 < end; e += 2) {
        int s0 = __ldg(col + e), s1 = __ldg(col + e + 1);
        float c0 = __ldg(escale + s0), c1 = __ldg(escale + s1);
        const uint4* hp0 = reinterpret_cast<const uint4*>(h + (size_t)s0 * 512) + 2 * lane;
        const uint4* hp1 = reinterpret_cast<const uint4*>(h + (size_t)s1 * 512) + 2 * lane;
        uint4 p0 = __ldg(hp0), q0 = __ldg(hp0 + 1);
        uint4 p1 = __ldg(hp1), q1 = __ldg(hp1 + 1);
        const uint32_t r0[8] = {p0.x, p0.y, p0.z, p0.w, q0.x, q0.y, q0.z, q0.w};
        const uint32_t r1[8] = {p1.x, p1.y, p1.z, p1.w, q1.x, q1.y, q1.z, q1.w};
#pragma unroll
        for (int i = 0; i < 8; i++) {
            float2 f0 = __half22float2(*(const __half2*)&r0[i]);
            float2 f1 = __half22float2(*(const __half2*)&r1[i]);
            acc[2 * i]     = fmaf(f0.x, c0, acc[2 * i]);
            acc[2 * i + 1] = fmaf(f0.y, c0, acc[2 * i + 1]);
            acc[2 * i]     = fmaf(f1.x, c1, acc[2 * i]);
            acc[2 * i + 1] = fmaf(f1.y, c1, acc[2 * i + 1]);
        }
    }
    if (e < end) {
        int s = __ldg(col + e);
        float c = __ldg(escale + s);
        const uint4* hp = reinterpret_cast<const uint4*>(h + (size_t)s * 512) + 2 * lane;
        uint4 p = __ldg(hp), q = __ldg(hp + 1);
        const uint32_t pr[8] = {p.x, p.y, p.z, p.w, q.x, q.y, q.z, q.w};
#pragma unroll
        for (int i = 0; i < 8; i++) {
            float2 f = __half22float2(*(const __half2*)&pr[i]);
            acc[2 * i]     = fmaf(f.x, c, acc[2 * i]);
            acc[2 * i + 1] = fmaf(f.y, c, acc[2 * i + 1]);
        }
    }
    float d = din[w];
    uint32_t o[8];
#pragma unroll
    for (int i = 0; i < 8; i++) {
        __half2 h2 = __floats2half2_rn(acc[2 * i] * d, acc[2 * i + 1] * d);
        o[i] = *(uint32_t*)&h2;
    }
    uint4* op = reinterpret_cast<uint4*>(aggh + (size_t)w * 512) + 2 * lane;
    op[0] = make_uint4(o[0], o[1], o[2], o[3]);
    op[1] = make_uint4(o[4], o[5], o[6], o[7]);
}

// ---------------- plain gather (layer 2) -------------------------------------
__global__ void k_gather_ns(const __half* __restrict__ h,
                            const int* __restrict__ rp, const int* __restrict__ col,
                            const float* __restrict__ din,
                            __half* __restrict__ aggh, int n_dst, int ebase) {
    int w = (blockIdx.x * blockDim.x + threadIdx.x) >> 5;
    int lane = threadIdx.x & 31;
    if (w >= n_dst) return;
    int beg = rp[w] - ebase, end = rp[w + 1] - ebase;
    float acc[16];
#pragma unroll
    for (int i = 0; i < 16; i++) acc[i] = 0.f;
    for (int e = beg; e < end; e++) {
        int s = __ldg(col + e);
        const uint4* hp = reinterpret_cast<const uint4*>(h + (size_t)s * 512) + 2 * lane;
        uint4 p = __ldg(hp), q = __ldg(hp + 1);
        const uint32_t pr[8] = {p.x, p.y, p.z, p.w, q.x, q.y, q.z, q.w};
#pragma unroll
        for (int i = 0; i < 8; i++) {
            float2 f = __half22float2(*(const __half2*)&pr[i]);
            acc[2 * i] += f.x;
            acc[2 * i + 1] += f.y;
        }
    }
    float d = din[w];
    uint32_t o[8];
#pragma unroll
    for (int i = 0; i < 8; i++) {
        __half2 h2 = __floats2half2_rn(acc[2 * i] * d, acc[2 * i + 1] * d);
        o[i] = *(uint32_t*)&h2;
    }
    uint4* op = reinterpret_cast<uint4*>(aggh + (size_t)w * 512) + 2 * lane;
    op[0] = make_uint4(o[0], o[1], o[2], o[3]);
    op[1] = make_uint4(o[4], o[5], o[6], o[7]);
}

// ---------------- fp16 HMMA GEMM: C = rowscale * relu(A @ B + bias) ----------
#define PADK 40
#define PADN 136
#define SZ_A (64 * PADK * 2)
#define SZ_B (32 * PADN * 2)
#define STAGE_BYTES (SZ_A + SZ_B)
#define GSM_TOTAL (2 * STAGE_BYTES)
#define O_AH 0
#define O_BH SZ_A

__device__ __forceinline__ void ldm4(uint32_t* f, uint32_t addr) {
    asm volatile("ldmatrix.sync.aligned.m8n8.x4.shared.b16 {%0,%1,%2,%3}, [%4];"
                 : "=r"(f[0]), "=r"(f[1]), "=r"(f[2]), "=r"(f[3]) : "r"(addr));
}
__device__ __forceinline__ void ldm4t(uint32_t* f, uint32_t addr) {
    asm volatile("ldmatrix.sync.aligned.m8n8.x4.trans.shared.b16 {%0,%1,%2,%3}, [%4];"
                 : "=r"(f[0]), "=r"(f[1]), "=r"(f[2]), "=r"(f[3]) : "r"(addr));
}
__device__ __forceinline__ void mma16816h(float* c, const uint32_t* a, const uint32_t* b) {
    asm volatile("mma.sync.aligned.m16n8k16.row.col.f32.f16.f16.f32 "
                 "{%0,%1,%2,%3}, {%4,%5,%6,%7}, {%8,%9}, {%0,%1,%2,%3};"
                 : "+f"(c[0]), "+f"(c[1]), "+f"(c[2]), "+f"(c[3])
                 : "r"(a[0]), "r"(a[1]), "r"(a[2]), "r"(a[3]), "r"(b[0]), "r"(b[1]));
}

__global__ __launch_bounds__(256, 2) void k_gemm_h(
    const __half* __restrict__ A, const __half* __restrict__ B,
    const float* __restrict__ bias, const float* __restrict__ rscale,
    void* __restrict__ Cv, int M, int Nt, int out_half) {
    extern __shared__ char smem[];
    int tid = threadIdx.x;
    int wid = tid >> 5, lane = tid & 31;
    int wm = (wid >> 2) * 32;
    int wn = (wid & 3) * 32;
    int row0 = blockIdx.y * 64, col0 = blockIdx.x * 128;

    int sr = tid >> 2;
    int sk = (tid & 3) * 8;
    int rowA = row0 + sr;
    bool aval = rowA < M;
    const __half* gA = A + (size_t)(aval ? rowA : 0) * 512 + sk;
    int bk = tid >> 3;
    int bn = (tid & 7) * 16;
    const __half* gB = B + (size_t)bk * Nt + col0 + bn;

    uint32_t ubase = (uint32_t)__cvta_generic_to_shared(smem);

    int aRow = wm + (lane & 15);
    int aCol = (lane >> 4) << 3;
    int kIdx = (lane & 7) + (((lane >> 3) & 1) << 3);
    int nOff = (lane >> 4) << 3;

    float acc[2][4][4];
#pragma unroll
    for (int i = 0; i < 2; i++)
#pragma unroll
        for (int j = 0; j < 4; j++)
#pragma unroll
            for (int k = 0; k < 4; k++) acc[i][j][k] = 0.f;

    {
        char* st = smem;
        uint4 va = aval ? __ldg((const uint4*)gA) : make_uint4(0, 0, 0, 0);
        *(uint4*)(st + O_AH + (sr * PADK + sk) * 2) = va;
        uint4 vb0 = __ldg((const uint4*)gB);
        uint4 vb1 = __ldg((const uint4*)gB + 1);
        *(uint4*)(st + O_BH + (bk * PADN + bn) * 2) = vb0;
        *(uint4*)(st + O_BH + (bk * PADN + bn) * 2 + 16) = vb1;
    }
    __syncthreads();

    for (int c = 0; c < 16; c++) {
        uint32_t ub = ubase + (c & 1) * STAGE_BYTES;

        uint4 pa, pb0, pb1;
        if (c < 15) {
            pa = aval ? __ldg((const uint4*)(gA + (c + 1) * 32)) : make_uint4(0, 0, 0, 0);
            const __half* nb = gB + (size_t)(c + 1) * 32 * Nt;
            pb0 = __ldg((const uint4*)nb);
            pb1 = __ldg((const uint4*)nb + 1);
        }

#pragma unroll
        for (int ks = 0; ks < 32; ks += 16) {
            uint32_t ah[2][4], bh[4][2];
#pragma unroll
            for (int mt = 0; mt < 2; mt++) {
                uint32_t off = ((uint32_t)((aRow + mt * 16) * PADK + ks + aCol)) * 2;
                ldm4(ah[mt], ub + O_AH + off);
            }
#pragma unroll
            for (int ntp = 0; ntp < 2; ntp++) {
                uint32_t off = ((uint32_t)((ks + kIdx) * PADN + wn + ntp * 16 + nOff)) * 2;
                uint32_t t[4];
                ldm4t(t, ub + O_BH + off);
                bh[ntp * 2][0] = t[0]; bh[ntp * 2][1] = t[1];
                bh[ntp * 2 + 1][0] = t[2]; bh[ntp * 2 + 1][1] = t[3];
            }
#pragma unroll
            for (int mt = 0; mt < 2; mt++)
#pragma unroll
                for (int nt = 0; nt < 4; nt++)
                    mma16816h(acc[mt][nt], ah[mt], bh[nt]);
        }

        if (c < 15) {
            char* st = smem + ((c & 1) ^ 1) * STAGE_BYTES;
            *(uint4*)(st + O_AH + (sr * PADK + sk) * 2) = pa;
            *(uint4*)(st + O_BH + (bk * PADN + bn) * 2) = pb0;
            *(uint4*)(st + O_BH + (bk * PADN + bn) * 2 + 16) = pb1;
        }
        __syncthreads();
    }

    int erow = row0 + wm + (lane >> 2);
    int ecol0 = col0 + wn + (lane & 3) * 2;
#pragma unroll
    for (int nt = 0; nt < 4; nt++) {
        int cc = ecol0 + nt * 8;
        float bx = __ldg(bias + cc), by = __ldg(bias + cc + 1);
#pragma unroll
        for (int mt = 0; mt < 2; mt++) {
#pragma unroll
            for (int hpart = 0; hpart < 2; hpart++) {
                int rr = erow + mt * 16 + hpart * 8;
                if (rr < M) {
                    float rs = rscale ? __ldg(rscale + rr) : 1.0f;
                    float ox = fmaxf(acc[mt][nt][2 * hpart] + bx, 0.f) * rs;
                    float oy = fmaxf(acc[mt][nt][2 * hpart + 1] + by, 0.f) * rs;
                    if (out_half) {
                        __half2 h2 = __floats2half2_rn(ox, oy);
                        *(uint32_t*)((__half*)Cv + (size_t)rr * Nt + cc) = *(uint32_t*)&h2;
                    } else {
                        *(float2*)((float*)Cv + (size_t)rr * Nt + cc) = make_float2(ox, oy);
                    }
                }
            }
        }
    }
}

// ---------------- launch ----------------------------------------------------

extern "C" void kernel_launch(void* const* d_in, const int* in_sizes, int n_in,
                              void* d_out, int out_size) {
    const float* x    = (const float*)d_in[0];
    const int*   src0 = (const int*)d_in[1];
    const int*   dst0 = (const int*)d_in[2];
    const int*   src1 = (const int*)d_in[3];
    const int*   dst1 = (const int*)d_in[4];
    const float* W1   = (const float*)d_in[5];
    const float* b1   = (const float*)d_in[6];
    const float* W2   = (const float*)d_in[7];
    const float* b2   = (const float*)d_in[8];
    float* out = (float*)d_out;

    float* nrm;
    int *ints, *rpc, *cur, *col0, *col1, *part;
    __half *xh, *agg0h, *h1h, *agg1h, *w1h, *w2h;
    cudaGetSymbolAddress((void**)&nrm,   g_norm);
    cudaGetSymbolAddress((void**)&ints,  g_ints);
    cudaGetSymbolAddress((void**)&rpc,   g_rpc);
    cudaGetSymbolAddress((void**)&cur,   g_cur);
    cudaGetSymbolAddress((void**)&col0,  g_col0);
    cudaGetSymbolAddress((void**)&col1,  g_col1);
    cudaGetSymbolAddress((void**)&part,  g_part);
    cudaGetSymbolAddress((void**)&xh,    g_xh);
    cudaGetSymbolAddress((void**)&agg0h, g_agg0h);
    cudaGetSymbolAddress((void**)&h1h,   g_h1h);
    cudaGetSymbolAddress((void**)&agg1h, g_agg1h);
    cudaGetSymbolAddress((void**)&w1h,   g_w1h);
    cudaGetSymbolAddress((void**)&w2h,   g_w2h);

    cudaFuncSetAttribute(k_gemm_h, cudaFuncAttributeMaxDynamicSharedMemorySize, GSM_TOTAL);

    const float* din0  = nrm + OFF_C_DST0;
    const float* din1  = nrm + OFF_C_DST1;
    const float* outn1 = nrm + OFF_C_SRC1;
    const float* outn0 = nrm + OFF_C_SRC0;

    // 1) zero counters
    k_zeroi<<<128, 256>>>(ints, N_CNT);

    // 2) fused prep: x->fp16 | W->fp16 | degree counts (overlapped in-kernel)
    k_prep<<<XP_BLOCKS + WP_BLOCKS + CNT_BLOCKS, 256>>>(x, xh, W1, W2, w1h, w2h,
                                                        src0, dst0, src1, dst1, ints);

    // 3) hierarchical scan over [dst0|dst1] counts (also emits cursors)
    {
        int nb = (N_SCAN + 1023) / 1024;   // 24
        k_scan1<<<nb, 1024>>>(ints, rpc, cur, part, N_SCAN);
        k_scan2<<<1, 32>>>(part, nb, rpc);
        k_scan3<<<nb, 1024>>>(rpc, cur, part, N_SCAN);
    }

    // 4) fused norms + both CSC fills
    k_fill_norm<<<(E0V + E1V + 255) / 256, 256>>>(src0, dst0, src1, dst1,
                                                  cur, ints, col0, col1, nrm);

    // 5) layer-1 gather: agg0h[d] = din0[d] * sum outn0[s]*xh[s]
    k_gather_es<<<(N_DST0 * 32 + 255) / 256, 256>>>(xh, rpc, col0, outn0, din0,
                                                    agg0h, N_DST0);

    // 6) GEMM1: h1h = outn1[row] * relu(agg0h @ W1h + b1)  (fp16 out)
    {
        dim3 grid(HID_F / 128, (N_DST0 + 63) / 64);
        k_gemm_h<<<grid, 256, GSM_TOTAL>>>(agg0h, w1h, b1, outn1, h1h,
                                           N_DST0, HID_F, 1);
    }

    // 7) layer-2 gather: agg1h[d] = din1[d] * sum h1h[s]
    k_gather_ns<<<(N_DST1 * 32 + 255) / 256, 256>>>(h1h, rpc + OFF_C_DST1, col1, din1,
                                                    agg1h, N_DST1, E0V);

    // 8) GEMM2: out = relu(agg1h @ W2h + b2)  (fp32 out)
    {
        dim3 grid(OUT_F / 128, (N_DST1 + 63) / 64);
        k_gemm_h<<<grid, 256, GSM_TOTAL>>>(agg1h, w2h, b2, nullptr, out,
                                           N_DST1, OUT_F, 0);
    }
}